// round 14
// baseline (speedup 1.0000x reference)
#include <cuda_runtime.h>
#include <cuda_fp16.h>
#include <cstdint>

#define NN 50000
#define EE 800000
#define ELn 100000
#define ET 850000   // EE + NN self loops
#define DD 256
#define NSPLIT_BLK 196               // GEMM-2 / agg-1 pipeline split (m-blocks)
#define NSPLIT (NSPLIT_BLK * 128)    // 25088 nodes

// ---------------- scratch (static device globals; no allocation) ------------
__device__ __half g_hh[(size_t)NN * DD];  // pre-aggregation features (fp16)
__device__ __half g_z16[(size_t)NN * DD]; // layer outputs (fp16)
__device__ float g_als[NN * 4];
__device__ float g_ald[NN * 4];
__device__ int   g_deg[NN + 1];
__device__ int   g_off[NN + 1];
__device__ int   g_cur[NN];
__device__ int   g_perm[ET];              // resolved SRC id per CSR slot

__device__ __forceinline__ float lrelu(float v) { return v > 0.f ? v : 0.2f * v; }
__device__ __forceinline__ float eluf(float v)  { return v > 0.f ? v : expm1f(v); }

__device__ __forceinline__ uint32_t s2u(const void* p) {
    return (uint32_t)__cvta_generic_to_shared(p);
}
__device__ __forceinline__ void ldm_x4(uint32_t& r0, uint32_t& r1, uint32_t& r2,
                                       uint32_t& r3, uint32_t addr) {
    asm volatile("ldmatrix.sync.aligned.m8n8.x4.shared.b16 {%0,%1,%2,%3}, [%4];"
                 : "=r"(r0), "=r"(r1), "=r"(r2), "=r"(r3) : "r"(addr));
}
__device__ __forceinline__ void ldm_x2t(uint32_t& r0, uint32_t& r1, uint32_t addr) {
    asm volatile("ldmatrix.sync.aligned.m8n8.x2.trans.shared.b16 {%0,%1}, [%2];"
                 : "=r"(r0), "=r"(r1) : "r"(addr));
}
__device__ __forceinline__ void mma_f16(float c[4], const uint32_t a[4], const uint32_t b[2]) {
    asm volatile(
        "mma.sync.aligned.m16n8k16.row.col.f32.f16.f16.f32 "
        "{%0,%1,%2,%3}, {%4,%5,%6,%7}, {%8,%9}, {%0,%1,%2,%3};"
        : "+f"(c[0]), "+f"(c[1]), "+f"(c[2]), "+f"(c[3])
        : "r"(a[0]), "r"(a[1]), "r"(a[2]), "r"(a[3]), "r"(b[0]), "r"(b[1]));
}
__device__ __forceinline__ uint4 pack8(float4 u, float4 v) {
    __half2 h0 = __floats2half2_rn(u.x, u.y), h1 = __floats2half2_rn(u.z, u.w);
    __half2 h2 = __floats2half2_rn(v.x, v.y), h3 = __floats2half2_rn(v.z, v.w);
    uint4 r;
    r.x = *(uint32_t*)&h0; r.y = *(uint32_t*)&h1;
    r.z = *(uint32_t*)&h2; r.w = *(uint32_t*)&h3;
    return r;
}

// ---------------- CSR build ------------------------------------------------
// self-loops pre-counted: deg starts at 1, cur starts at 1, slot g_off[i] = self.
__global__ void k_zero() {
    int i = blockIdx.x * blockDim.x + threadIdx.x;
    if (i < NN) { g_deg[i] = 1; g_cur[i] = 1; }
    if (i == NN) g_deg[NN] = 0;
}

__global__ void k_hist(const int* __restrict__ ei) {
    int e4 = (blockIdx.x * blockDim.x + threadIdx.x) * 4;
    if (e4 >= EE) return;
    int4 d4 = *(const int4*)(ei + EE + e4);
    atomicAdd(&g_deg[d4.x], 1);
    atomicAdd(&g_deg[d4.y], 1);
    atomicAdd(&g_deg[d4.z], 1);
    atomicAdd(&g_deg[d4.w], 1);
}

// single block, 1024 threads, warp-shuffle scan
__global__ void k_scan() {
    __shared__ int wsum[32];
    __shared__ int wtot_s;
    int t = threadIdx.x, lane = t & 31, wid = t >> 5;
    int carry = 0;
    for (int base = 0; base < NN; base += 1024) {
        int v = (base + t < NN) ? g_deg[base + t] : 0;
        int incl = v;
        #pragma unroll
        for (int o = 1; o < 32; o <<= 1) {
            int u = __shfl_up_sync(0xffffffffu, incl, o);
            if (lane >= o) incl += u;
        }
        if (lane == 31) wsum[wid] = incl;
        __syncthreads();
        if (wid == 0) {
            int s = wsum[lane];
            int si = s;
            #pragma unroll
            for (int o = 1; o < 32; o <<= 1) {
                int u = __shfl_up_sync(0xffffffffu, si, o);
                if (lane >= o) si += u;
            }
            wsum[lane] = si - s;
            if (lane == 31) wtot_s = si;
        }
        __syncthreads();
        if (base + t < NN) g_off[base + t] = carry + wsum[wid] + incl - v;
        carry += wtot_s;
        __syncthreads();
    }
    if (t == 0) g_off[NN] = carry;
}

__global__ void k_self() {
    int i = blockIdx.x * blockDim.x + threadIdx.x;
    if (i < NN) g_perm[g_off[i]] = i;   // self-loop at slot 0 of each node
}

__global__ void k_scatter(const int* __restrict__ ei) {
    int e4 = (blockIdx.x * blockDim.x + threadIdx.x) * 4;
    if (e4 >= EE) return;
    int4 s4 = *(const int4*)(ei + e4);
    int4 d4 = *(const int4*)(ei + EE + e4);
    int p;
    p = atomicAdd(&g_cur[d4.x], 1); g_perm[g_off[d4.x] + p] = s4.x;
    p = atomicAdd(&g_cur[d4.y], 1); g_perm[g_off[d4.y] + p] = s4.y;
    p = atomicAdd(&g_cur[d4.z], 1); g_perm[g_off[d4.z] + p] = s4.z;
    p = atomicAdd(&g_cur[d4.w], 1); g_perm[g_off[d4.w] + p] = s4.w;
}

// ------------- fp16 tensor-core GEMM + fused attention logits --------------
// g_hh[M,256](fp16) = A[M,K] @ B[K,256]; FINAL g_als/g_ald for heads {2nb,2nb+1}
// A16=0: A = Ain (fp32).  A16=1: A = g_z16 (fp16), K = 256.
// mboff: m-block offset (row-range pipelining of GEMM-2).
template<int A16>
__global__ __launch_bounds__(256) void k_gemm_tc(
        const float* __restrict__ Ain, const float* __restrict__ B,
        const float* __restrict__ a_src, const float* __restrict__ a_dst,
        int M, int K, int mboff) {
    __shared__ __align__(16) __half As[2][128][40];
    __shared__ __align__(16) __half Bs[2][32][136];
    __shared__ float SPSa[128][9], SPDa[128][9];
    int tid = threadIdx.x, lane = tid & 31, w = tid >> 5;
    int m0 = (blockIdx.x + mboff) * 128, nb = blockIdx.y, n0 = nb * 128;
    int wm = (w & 1) * 64, wn = (w >> 1) * 32;
    int g = lane >> 2, t4 = lane & 3;

    float acc[4][4][4];
    #pragma unroll
    for (int i = 0; i < 4; i++)
        #pragma unroll
        for (int j = 0; j < 4; j++)
            #pragma unroll
            for (int q = 0; q < 4; q++) acc[i][j][q] = 0.f;

    int am2 = tid >> 2, akv8 = (tid & 3) * 8;
    int bkk = tid >> 4, bn8 = (tid & 15) * 8;

    uint4 qa[2]; float4 pa[2][2]; float4 pb[2][2];
    if (A16) {
        #pragma unroll
        for (int p = 0; p < 2; p++) {
            int gm = m0 + am2 + p * 64;
            qa[p] = (gm < M) ? *(const uint4*)(g_z16 + (size_t)gm * DD + akv8)
                             : make_uint4(0u, 0u, 0u, 0u);
        }
    } else {
        #pragma unroll
        for (int p = 0; p < 2; p++) {
            int gm = m0 + am2 + p * 64;
            if (gm < M) {
                pa[p][0] = *(const float4*)(Ain + (size_t)gm * K + akv8);
                pa[p][1] = *(const float4*)(Ain + (size_t)gm * K + akv8 + 4);
            } else {
                pa[p][0] = make_float4(0.f, 0.f, 0.f, 0.f);
                pa[p][1] = make_float4(0.f, 0.f, 0.f, 0.f);
            }
        }
    }
    #pragma unroll
    for (int p = 0; p < 2; p++) {
        int kr = bkk + p * 16;
        pb[p][0] = *(const float4*)(B + (size_t)kr * DD + n0 + bn8);
        pb[p][1] = *(const float4*)(B + (size_t)kr * DD + n0 + bn8 + 4);
    }
    #pragma unroll
    for (int p = 0; p < 2; p++) {
        uint4 v = A16 ? qa[p] : pack8(pa[p][0], pa[p][1]);
        *(uint4*)&As[0][am2 + p * 64][akv8] = v;
        *(uint4*)&Bs[0][bkk + p * 16][bn8] = pack8(pb[p][0], pb[p][1]);
    }
    __syncthreads();

    int nk = K >> 5;
    for (int kt = 0; kt < nk; kt++) {
        int cur = kt & 1, nxt = cur ^ 1;
        int kn = (kt + 1) << 5;
        bool more = kn < K;
        if (more) {
            if (A16) {
                #pragma unroll
                for (int p = 0; p < 2; p++) {
                    int gm = m0 + am2 + p * 64;
                    qa[p] = (gm < M) ? *(const uint4*)(g_z16 + (size_t)gm * DD + kn + akv8)
                                     : make_uint4(0u, 0u, 0u, 0u);
                }
            } else {
                #pragma unroll
                for (int p = 0; p < 2; p++) {
                    int gm = m0 + am2 + p * 64;
                    if (gm < M) {
                        pa[p][0] = *(const float4*)(Ain + (size_t)gm * K + kn + akv8);
                        pa[p][1] = *(const float4*)(Ain + (size_t)gm * K + kn + akv8 + 4);
                    } else {
                        pa[p][0] = make_float4(0.f, 0.f, 0.f, 0.f);
                        pa[p][1] = make_float4(0.f, 0.f, 0.f, 0.f);
                    }
                }
            }
            #pragma unroll
            for (int p = 0; p < 2; p++) {
                int kr = kn + bkk + p * 16;
                pb[p][0] = *(const float4*)(B + (size_t)kr * DD + n0 + bn8);
                pb[p][1] = *(const float4*)(B + (size_t)kr * DD + n0 + bn8 + 4);
            }
        }
        int arow = lane & 15, asel = (lane >> 4) * 8;
        #pragma unroll
        for (int kh = 0; kh < 2; kh++) {
            int k16 = kh * 16;
            uint32_t af[4][4], bf[4][2];
            #pragma unroll
            for (int i = 0; i < 4; i++)
                ldm_x4(af[i][0], af[i][1], af[i][2], af[i][3],
                       s2u(&As[cur][wm + i * 16 + arow][k16 + asel]));
            #pragma unroll
            for (int j = 0; j < 4; j++)
                ldm_x2t(bf[j][0], bf[j][1],
                        s2u(&Bs[cur][k16 + arow][wn + j * 8]));
            #pragma unroll
            for (int i = 0; i < 4; i++)
                #pragma unroll
                for (int j = 0; j < 4; j++) mma_f16(acc[i][j], af[i], bf[j]);
        }
        if (more) {
            #pragma unroll
            for (int p = 0; p < 2; p++) {
                uint4 v = A16 ? qa[p] : pack8(pa[p][0], pa[p][1]);
                *(uint4*)&As[nxt][am2 + p * 64][akv8] = v;
                *(uint4*)&Bs[nxt][bkk + p * 16][bn8] = pack8(pb[p][0], pb[p][1]);
            }
        }
        __syncthreads();
    }

    // epilogue: store h (fp16) + logit partials (warp's 32 cols = one head)
    int t2 = t4 * 2;
    float ps[8], pd[8];
    #pragma unroll
    for (int i = 0; i < 8; i++) { ps[i] = 0.f; pd[i] = 0.f; }
    #pragma unroll
    for (int i = 0; i < 4; i++) {
        int r = m0 + wm + i * 16 + g;
        #pragma unroll
        for (int j = 0; j < 4; j++) {
            int c = n0 + wn + j * 8 + t2;
            float a0 = a_src[c], a1 = a_src[c + 1];
            float d0 = a_dst[c], d1 = a_dst[c + 1];
            ps[i]     += acc[i][j][0] * a0 + acc[i][j][1] * a1;
            pd[i]     += acc[i][j][0] * d0 + acc[i][j][1] * d1;
            ps[i + 4] += acc[i][j][2] * a0 + acc[i][j][3] * a1;
            pd[i + 4] += acc[i][j][2] * d0 + acc[i][j][3] * d1;
            if (r < M)
                *(__half2*)(g_hh + (size_t)r * DD + c) =
                    __floats2half2_rn(acc[i][j][0], acc[i][j][1]);
            if (r + 8 < M)
                *(__half2*)(g_hh + (size_t)(r + 8) * DD + c) =
                    __floats2half2_rn(acc[i][j][2], acc[i][j][3]);
        }
    }
    #pragma unroll
    for (int i = 0; i < 8; i++) {
        #pragma unroll
        for (int o = 1; o < 4; o <<= 1) {
            ps[i] += __shfl_xor_sync(0xffffffffu, ps[i], o);
            pd[i] += __shfl_xor_sync(0xffffffffu, pd[i], o);
        }
    }
    if (t4 == 0) {
        #pragma unroll
        for (int i = 0; i < 4; i++) {
            int rl = wm + i * 16 + g;
            SPSa[rl][w] = ps[i];        SPDa[rl][w] = pd[i];
            SPSa[rl + 8][w] = ps[i + 4]; SPDa[rl + 8][w] = pd[i + 4];
        }
    }
    __syncthreads();
    if (tid < 128) {
        int r = tid;
        int b = (r >= 64) ? 1 : 0;
        float h0s = SPSa[r][b] + SPSa[r][b + 2];
        float h1s = SPSa[r][b + 4] + SPSa[r][b + 6];
        float h0d = SPDa[r][b] + SPDa[r][b + 2];
        float h1d = SPDa[r][b + 4] + SPDa[r][b + 6];
        int gr = m0 + r;
        if (gr < M) {
            g_als[gr * 4 + 2 * nb]     = h0s;
            g_als[gr * 4 + 2 * nb + 1] = h1s;
            g_ald[gr * 4 + 2 * nb]     = h0d;
            g_ald[gr * 4 + 2 * nb + 1] = h1d;
        }
    }
}

// ------- fused edge-softmax + aggregation, single pass (g_hh -> g_z16) -----
// node range [nbeg, nend)
__global__ void k_agg(const float* __restrict__ bias, int nbeg, int nend) {
    int warp = nbeg + ((blockIdx.x * blockDim.x + threadIdx.x) >> 5);
    int lane = threadIdx.x & 31;
    if (warp >= nend) return;
    int n = warp;
    int start = g_off[n], end = g_off[n + 1];
    int myh = lane >> 3;
    float adh = g_ald[n * 4 + myh];
    const size_t cbase = (size_t)lane * 8;

    float den = 0.f;
    float4 acc0 = make_float4(0.f, 0.f, 0.f, 0.f);
    float4 acc1 = make_float4(0.f, 0.f, 0.f, 0.f);

    int i = start;
    for (; i + 2 <= end; i += 2) {
        int s0 = g_perm[i], s1 = g_perm[i + 1];
        float w0 = __expf(lrelu(g_als[s0 * 4 + myh] + adh));
        float w1 = __expf(lrelu(g_als[s1 * 4 + myh] + adh));
        uint4 r0 = *(const uint4*)(g_hh + (size_t)s0 * DD + cbase);
        uint4 r1 = *(const uint4*)(g_hh + (size_t)s1 * DD + cbase);
        const __half2* h0 = (const __half2*)&r0;
        const __half2* h1 = (const __half2*)&r1;
        float2 a = __half22float2(h0[0]), b = __half22float2(h0[1]);
        float2 c = __half22float2(h0[2]), d = __half22float2(h0[3]);
        float2 e = __half22float2(h1[0]), f = __half22float2(h1[1]);
        float2 p = __half22float2(h1[2]), q = __half22float2(h1[3]);
        den += w0 + w1;
        acc0.x += w0 * a.x + w1 * e.x; acc0.y += w0 * a.y + w1 * e.y;
        acc0.z += w0 * b.x + w1 * f.x; acc0.w += w0 * b.y + w1 * f.y;
        acc1.x += w0 * c.x + w1 * p.x; acc1.y += w0 * c.y + w1 * p.y;
        acc1.z += w0 * d.x + w1 * q.x; acc1.w += w0 * d.y + w1 * q.y;
    }
    if (i < end) {
        int s0 = g_perm[i];
        float w0 = __expf(lrelu(g_als[s0 * 4 + myh] + adh));
        uint4 r0 = *(const uint4*)(g_hh + (size_t)s0 * DD + cbase);
        const __half2* h0 = (const __half2*)&r0;
        float2 a = __half22float2(h0[0]), b = __half22float2(h0[1]);
        float2 c = __half22float2(h0[2]), d = __half22float2(h0[3]);
        den += w0;
        acc0.x += w0 * a.x; acc0.y += w0 * a.y;
        acc0.z += w0 * b.x; acc0.w += w0 * b.y;
        acc1.x += w0 * c.x; acc1.y += w0 * c.y;
        acc1.z += w0 * d.x; acc1.w += w0 * d.y;
    }
    float inv = 1.f / den;
    const float4* bp = (const float4*)(bias + cbase);
    float4 b0 = bp[0], b1 = bp[1];
    __half2 ho0 = __floats2half2_rn(eluf(acc0.x * inv + b0.x), eluf(acc0.y * inv + b0.y));
    __half2 ho1 = __floats2half2_rn(eluf(acc0.z * inv + b0.z), eluf(acc0.w * inv + b0.w));
    __half2 ho2 = __floats2half2_rn(eluf(acc1.x * inv + b1.x), eluf(acc1.y * inv + b1.y));
    __half2 ho3 = __floats2half2_rn(eluf(acc1.z * inv + b1.z), eluf(acc1.w * inv + b1.w));
    uint4 pk;
    pk.x = *(uint32_t*)&ho0; pk.y = *(uint32_t*)&ho1;
    pk.z = *(uint32_t*)&ho2; pk.w = *(uint32_t*)&ho3;
    *(uint4*)(g_z16 + (size_t)n * DD + cbase) = pk;
}

// -------- link scorer: fp16 gather-GEMM (A from g_z16) + fused MLP ---------
__global__ __launch_bounds__(256) void k_score_tc(
        const int* __restrict__ eli,
        const float* __restrict__ Ws1, const float* __restrict__ bs1,
        const float* __restrict__ Ws2, const float* __restrict__ bs2,
        float* __restrict__ out) {
    __shared__ __align__(16) __half As[128][40];
    __shared__ __align__(16) __half Bs[32][72];
    __shared__ int si0[128], si1[128];
    __shared__ float red[128][2];
    int tid = threadIdx.x, lane = tid & 31, w = tid >> 5;
    int m0 = blockIdx.x * 128;
    int wm = (w & 3) * 32, wn = (w >> 2) * 32;
    int g = lane >> 2, t4 = lane & 3;

    if (tid < 128) {
        int gm = m0 + tid;
        si0[tid] = (gm < ELn) ? eli[gm] : 0;
        si1[tid] = (gm < ELn) ? eli[ELn + gm] : 0;
    }
    __syncthreads();

    float acc[2][4][4];
    #pragma unroll
    for (int i = 0; i < 2; i++)
        #pragma unroll
        for (int j = 0; j < 4; j++)
            #pragma unroll
            for (int q = 0; q < 4; q++) acc[i][j][q] = 0.f;

    int am2 = tid >> 2, akv8 = (tid & 3) * 8;
    int bkk = tid >> 3, bn8 = (tid & 7) * 8;

    uint4 qa[2]; float4 pb[2];
    #pragma unroll
    for (int p = 0; p < 2; p++) {
        int m = am2 + p * 64;
        qa[p] = *(const uint4*)(g_z16 + (size_t)si0[m] * DD + akv8);
    }
    pb[0] = *(const float4*)(Ws1 + (size_t)bkk * 64 + bn8);
    pb[1] = *(const float4*)(Ws1 + (size_t)bkk * 64 + bn8 + 4);

    for (int k0 = 0; k0 < 512; k0 += 32) {
        #pragma unroll
        for (int p = 0; p < 2; p++)
            *(uint4*)&As[am2 + p * 64][akv8] = qa[p];
        *(uint4*)&Bs[bkk][bn8] = pack8(pb[0], pb[1]);
        __syncthreads();
        int kn = k0 + 32;
        if (kn < 512) {
            int kk = kn + akv8;
            #pragma unroll
            for (int p = 0; p < 2; p++) {
                int m = am2 + p * 64;
                int row = (kk < 256) ? si0[m] : si1[m];
                qa[p] = *(const uint4*)(g_z16 + (size_t)row * DD + (kk & 255));
            }
            pb[0] = *(const float4*)(Ws1 + (size_t)(kn + bkk) * 64 + bn8);
            pb[1] = *(const float4*)(Ws1 + (size_t)(kn + bkk) * 64 + bn8 + 4);
        }
        int arow = lane & 15, asel = (lane >> 4) * 8;
        #pragma unroll
        for (int kh = 0; kh < 2; kh++) {
            int k16 = kh * 16;
            uint32_t af[2][4], bf[4][2];
            #pragma unroll
            for (int i = 0; i < 2; i++)
                ldm_x4(af[i][0], af[i][1], af[i][2], af[i][3],
                       s2u(&As[wm + i * 16 + arow][k16 + asel]));
            #pragma unroll
            for (int j = 0; j < 4; j++)
                ldm_x2t(bf[j][0], bf[j][1],
                        s2u(&Bs[k16 + arow][wn + j * 8]));
            #pragma unroll
            for (int i = 0; i < 2; i++)
                #pragma unroll
                for (int j = 0; j < 4; j++) mma_f16(acc[i][j], af[i], bf[j]);
        }
        __syncthreads();
    }
    int t2 = t4 * 2;
    float p00 = 0.f, p01 = 0.f, p10 = 0.f, p11 = 0.f;
    #pragma unroll
    for (int j = 0; j < 4; j++) {
        int c0 = wn + j * 8 + t2;
        float bv0 = bs1[c0], bv1 = bs1[c0 + 1];
        float w0 = Ws2[c0], w1 = Ws2[c0 + 1];
        p00 += fmaxf(acc[0][j][0] + bv0, 0.f) * w0 + fmaxf(acc[0][j][1] + bv1, 0.f) * w1;
        p01 += fmaxf(acc[0][j][2] + bv0, 0.f) * w0 + fmaxf(acc[0][j][3] + bv1, 0.f) * w1;
        p10 += fmaxf(acc[1][j][0] + bv0, 0.f) * w0 + fmaxf(acc[1][j][1] + bv1, 0.f) * w1;
        p11 += fmaxf(acc[1][j][2] + bv0, 0.f) * w0 + fmaxf(acc[1][j][3] + bv1, 0.f) * w1;
    }
    #pragma unroll
    for (int o = 1; o < 4; o <<= 1) {
        p00 += __shfl_xor_sync(0xffffffffu, p00, o);
        p01 += __shfl_xor_sync(0xffffffffu, p01, o);
        p10 += __shfl_xor_sync(0xffffffffu, p10, o);
        p11 += __shfl_xor_sync(0xffffffffu, p11, o);
    }
    int wnidx = w >> 2;
    if (t4 == 0) {
        red[wm + g][wnidx]      = p00;
        red[wm + 8 + g][wnidx]  = p01;
        red[wm + 16 + g][wnidx] = p10;
        red[wm + 24 + g][wnidx] = p11;
    }
    __syncthreads();
    if (tid < 128) {
        int gm = m0 + tid;
        if (gm < ELn) out[gm] = red[tid][0] + red[tid][1] + bs2[0];
    }
}

// ---------------- launch ---------------------------------------------------
extern "C" void kernel_launch(void* const* d_in, const int* in_sizes, int n_in,
                              void* d_out, int out_size) {
    const float* x   = (const float*)d_in[0];
    const int*   ei  = (const int*)d_in[1];
    const int*   eli = (const int*)d_in[2];
    const float* W1  = (const float*)d_in[3];
    const float* as1 = (const float*)d_in[4];
    const float* ad1 = (const float*)d_in[5];
    const float* b1  = (const float*)d_in[6];
    const float* W2  = (const float*)d_in[7];
    const float* as2 = (const float*)d_in[8];
    const float* ad2 = (const float*)d_in[9];
    const float* b2  = (const float*)d_in[10];
    const float* Ws1 = (const float*)d_in[11];
    const float* bs1 = (const float*)d_in[12];
    const float* Ws2 = (const float*)d_in[13];
    const float* bs2 = (const float*)d_in[14];
    float* out = (float*)d_out;

    // side stream (created per call and intentionally leaked; no device memory)
    cudaStream_t s1;
    cudaStreamCreateWithFlags(&s1, cudaStreamNonBlocking);
    cudaEvent_t evFork, evJoin, evA, evG2A;
    cudaEventCreateWithFlags(&evFork, cudaEventDisableTiming);
    cudaEventCreateWithFlags(&evJoin, cudaEventDisableTiming);
    cudaEventCreateWithFlags(&evA, cudaEventDisableTiming);
    cudaEventCreateWithFlags(&evG2A, cudaEventDisableTiming);

    cudaEventRecord(evFork, 0);
    cudaStreamWaitEvent(s1, evFork, 0);
    // CSR chain on s1 (concurrent with GEMM-1)
    k_zero<<<(NN + 256) / 256, 256, 0, s1>>>();
    k_hist<<<(EE / 4 + 255) / 256, 256, 0, s1>>>(ei);
    k_scan<<<1, 1024, 0, s1>>>();
    k_self<<<(NN + 255) / 256, 256, 0, s1>>>();
    k_scatter<<<(EE / 4 + 255) / 256, 256, 0, s1>>>(ei);
    cudaEventRecord(evJoin, s1);

    // layer-1 GEMM on main stream, concurrent with CSR build
    k_gemm_tc<0><<<dim3((NN + 127) / 128, 2), 256>>>(x, W1, as1, ad1, NN, 128, 0);
    cudaStreamWaitEvent(0, evJoin, 0);

    // agg-1 split: first half, then second half ‖ GEMM-2 first half on s1
    k_agg<<<(NSPLIT + 7) / 8, 256>>>(b1, 0, NSPLIT);
    cudaEventRecord(evA, 0);
    cudaStreamWaitEvent(s1, evA, 0);
    k_gemm_tc<1><<<dim3(NSPLIT_BLK, 2), 256, 0, s1>>>(nullptr, W2, as2, ad2, NN, 256, 0);
    cudaEventRecord(evG2A, s1);

    k_agg<<<(NN - NSPLIT + 7) / 8, 256>>>(b1, NSPLIT, NN);
    // GEMM-2 second half on main stream (agg-1 B complete here)
    k_gemm_tc<1><<<dim3((NN + 127) / 128 - NSPLIT_BLK, 2), 256>>>(nullptr, W2, as2, ad2, NN, 256, NSPLIT_BLK);
    cudaStreamWaitEvent(0, evG2A, 0);

    // agg-2 (needs both GEMM-2 halves) ; scorer
    k_agg<<<(NN + 7) / 8, 256>>>(b2, 0, NN);
    k_score_tc<<<(ELn + 127) / 128, 256>>>(eli, Ws1, bs1, Ws2, bs2, out);
}

// round 15
// speedup vs baseline: 1.0211x; 1.0211x over previous
#include <cuda_runtime.h>
#include <cuda_fp16.h>
#include <cstdint>

#define NN 50000
#define EE 800000
#define ELn 100000
#define ET 850000   // EE + NN self loops
#define DD 256

// ---------------- scratch (static device globals; no allocation) ------------
__device__ __half g_hh[(size_t)NN * DD];  // pre-aggregation features (fp16)
__device__ __half g_z16[(size_t)NN * DD]; // layer outputs (fp16)
__device__ float g_als[NN * 4];
__device__ float g_ald[NN * 4];
__device__ int   g_deg[NN + 1];
__device__ int   g_off[NN + 1];
__device__ int   g_cur[NN];
__device__ int   g_perm[ET];              // resolved SRC id per CSR slot

__device__ __forceinline__ float lrelu(float v) { return v > 0.f ? v : 0.2f * v; }
__device__ __forceinline__ float eluf(float v)  { return v > 0.f ? v : expm1f(v); }

__device__ __forceinline__ uint32_t s2u(const void* p) {
    return (uint32_t)__cvta_generic_to_shared(p);
}
__device__ __forceinline__ void ldm_x4(uint32_t& r0, uint32_t& r1, uint32_t& r2,
                                       uint32_t& r3, uint32_t addr) {
    asm volatile("ldmatrix.sync.aligned.m8n8.x4.shared.b16 {%0,%1,%2,%3}, [%4];"
                 : "=r"(r0), "=r"(r1), "=r"(r2), "=r"(r3) : "r"(addr));
}
__device__ __forceinline__ void ldm_x2t(uint32_t& r0, uint32_t& r1, uint32_t addr) {
    asm volatile("ldmatrix.sync.aligned.m8n8.x2.trans.shared.b16 {%0,%1}, [%2];"
                 : "=r"(r0), "=r"(r1) : "r"(addr));
}
__device__ __forceinline__ void mma_f16(float c[4], const uint32_t a[4], const uint32_t b[2]) {
    asm volatile(
        "mma.sync.aligned.m16n8k16.row.col.f32.f16.f16.f32 "
        "{%0,%1,%2,%3}, {%4,%5,%6,%7}, {%8,%9}, {%0,%1,%2,%3};"
        : "+f"(c[0]), "+f"(c[1]), "+f"(c[2]), "+f"(c[3])
        : "r"(a[0]), "r"(a[1]), "r"(a[2]), "r"(a[3]), "r"(b[0]), "r"(b[1]));
}
__device__ __forceinline__ uint4 pack8(float4 u, float4 v) {
    __half2 h0 = __floats2half2_rn(u.x, u.y), h1 = __floats2half2_rn(u.z, u.w);
    __half2 h2 = __floats2half2_rn(v.x, v.y), h3 = __floats2half2_rn(v.z, v.w);
    uint4 r;
    r.x = *(uint32_t*)&h0; r.y = *(uint32_t*)&h1;
    r.z = *(uint32_t*)&h2; r.w = *(uint32_t*)&h3;
    return r;
}

// ---------------- CSR build ------------------------------------------------
// self-loops pre-counted: deg starts at 1, cur starts at 1, slot g_off[i] = self.
__global__ void k_zero() {
    int i = blockIdx.x * blockDim.x + threadIdx.x;
    if (i < NN) { g_deg[i] = 1; g_cur[i] = 1; }
    if (i == NN) g_deg[NN] = 0;
}

__global__ void k_hist(const int* __restrict__ ei) {
    int e4 = (blockIdx.x * blockDim.x + threadIdx.x) * 4;
    if (e4 >= EE) return;
    int4 d4 = *(const int4*)(ei + EE + e4);
    atomicAdd(&g_deg[d4.x], 1);
    atomicAdd(&g_deg[d4.y], 1);
    atomicAdd(&g_deg[d4.z], 1);
    atomicAdd(&g_deg[d4.w], 1);
}

// single block, 1024 threads, warp-shuffle scan
__global__ void k_scan() {
    __shared__ int wsum[32];
    __shared__ int wtot_s;
    int t = threadIdx.x, lane = t & 31, wid = t >> 5;
    int carry = 0;
    for (int base = 0; base < NN; base += 1024) {
        int v = (base + t < NN) ? g_deg[base + t] : 0;
        int incl = v;
        #pragma unroll
        for (int o = 1; o < 32; o <<= 1) {
            int u = __shfl_up_sync(0xffffffffu, incl, o);
            if (lane >= o) incl += u;
        }
        if (lane == 31) wsum[wid] = incl;
        __syncthreads();
        if (wid == 0) {
            int s = wsum[lane];
            int si = s;
            #pragma unroll
            for (int o = 1; o < 32; o <<= 1) {
                int u = __shfl_up_sync(0xffffffffu, si, o);
                if (lane >= o) si += u;
            }
            wsum[lane] = si - s;
            if (lane == 31) wtot_s = si;
        }
        __syncthreads();
        if (base + t < NN) g_off[base + t] = carry + wsum[wid] + incl - v;
        carry += wtot_s;
        __syncthreads();
    }
    if (t == 0) g_off[NN] = carry;
}

// edge scatter + fused self-loop writes (extra thread range)
#define E4CNT (EE / 4)
__global__ void k_scatter(const int* __restrict__ ei) {
    int t = blockIdx.x * blockDim.x + threadIdx.x;
    if (t < E4CNT) {
        int e4 = t * 4;
        int4 s4 = *(const int4*)(ei + e4);
        int4 d4 = *(const int4*)(ei + EE + e4);
        int p;
        p = atomicAdd(&g_cur[d4.x], 1); g_perm[g_off[d4.x] + p] = s4.x;
        p = atomicAdd(&g_cur[d4.y], 1); g_perm[g_off[d4.y] + p] = s4.y;
        p = atomicAdd(&g_cur[d4.z], 1); g_perm[g_off[d4.z] + p] = s4.z;
        p = atomicAdd(&g_cur[d4.w], 1); g_perm[g_off[d4.w] + p] = s4.w;
    } else if (t < E4CNT + NN) {
        int i = t - E4CNT;
        g_perm[g_off[i]] = i;   // self-loop at slot 0 of each node
    }
}

// ------------- fp16 tensor-core GEMM + fused attention logits --------------
// g_hh[M,256](fp16) = A[M,K] @ B[K,256]; FINAL g_als/g_ald for heads {2nb,2nb+1}
// A16=0: A = Ain (fp32).  A16=1: A = g_z16 (fp16), K = 256.
// BM=128 BN=128 BK=32, 256 threads (2x4 warp grid, 64x32 warp tile)
template<int A16>
__global__ __launch_bounds__(256) void k_gemm_tc(
        const float* __restrict__ Ain, const float* __restrict__ B,
        const float* __restrict__ a_src, const float* __restrict__ a_dst,
        int M, int K) {
    __shared__ __align__(16) __half As[2][128][40];
    __shared__ __align__(16) __half Bs[2][32][136];
    __shared__ float SPSa[128][9], SPDa[128][9];
    int tid = threadIdx.x, lane = tid & 31, w = tid >> 5;
    int m0 = blockIdx.x * 128, nb = blockIdx.y, n0 = nb * 128;
    int wm = (w & 1) * 64, wn = (w >> 1) * 32;
    int g = lane >> 2, t4 = lane & 3;

    float acc[4][4][4];
    #pragma unroll
    for (int i = 0; i < 4; i++)
        #pragma unroll
        for (int j = 0; j < 4; j++)
            #pragma unroll
            for (int q = 0; q < 4; q++) acc[i][j][q] = 0.f;

    int am2 = tid >> 2, akv8 = (tid & 3) * 8;
    int bkk = tid >> 4, bn8 = (tid & 15) * 8;

    uint4 qa[2]; float4 pa[2][2]; float4 pb[2][2];
    if (A16) {
        #pragma unroll
        for (int p = 0; p < 2; p++) {
            int gm = m0 + am2 + p * 64;
            qa[p] = (gm < M) ? *(const uint4*)(g_z16 + (size_t)gm * DD + akv8)
                             : make_uint4(0u, 0u, 0u, 0u);
        }
    } else {
        #pragma unroll
        for (int p = 0; p < 2; p++) {
            int gm = m0 + am2 + p * 64;
            if (gm < M) {
                pa[p][0] = *(const float4*)(Ain + (size_t)gm * K + akv8);
                pa[p][1] = *(const float4*)(Ain + (size_t)gm * K + akv8 + 4);
            } else {
                pa[p][0] = make_float4(0.f, 0.f, 0.f, 0.f);
                pa[p][1] = make_float4(0.f, 0.f, 0.f, 0.f);
            }
        }
    }
    #pragma unroll
    for (int p = 0; p < 2; p++) {
        int kr = bkk + p * 16;
        pb[p][0] = *(const float4*)(B + (size_t)kr * DD + n0 + bn8);
        pb[p][1] = *(const float4*)(B + (size_t)kr * DD + n0 + bn8 + 4);
    }
    #pragma unroll
    for (int p = 0; p < 2; p++) {
        uint4 v = A16 ? qa[p] : pack8(pa[p][0], pa[p][1]);
        *(uint4*)&As[0][am2 + p * 64][akv8] = v;
        *(uint4*)&Bs[0][bkk + p * 16][bn8] = pack8(pb[p][0], pb[p][1]);
    }
    __syncthreads();

    int nk = K >> 5;
    for (int kt = 0; kt < nk; kt++) {
        int cur = kt & 1, nxt = cur ^ 1;
        int kn = (kt + 1) << 5;
        bool more = kn < K;
        if (more) {
            if (A16) {
                #pragma unroll
                for (int p = 0; p < 2; p++) {
                    int gm = m0 + am2 + p * 64;
                    qa[p] = (gm < M) ? *(const uint4*)(g_z16 + (size_t)gm * DD + kn + akv8)
                                     : make_uint4(0u, 0u, 0u, 0u);
                }
            } else {
                #pragma unroll
                for (int p = 0; p < 2; p++) {
                    int gm = m0 + am2 + p * 64;
                    if (gm < M) {
                        pa[p][0] = *(const float4*)(Ain + (size_t)gm * K + kn + akv8);
                        pa[p][1] = *(const float4*)(Ain + (size_t)gm * K + kn + akv8 + 4);
                    } else {
                        pa[p][0] = make_float4(0.f, 0.f, 0.f, 0.f);
                        pa[p][1] = make_float4(0.f, 0.f, 0.f, 0.f);
                    }
                }
            }
            #pragma unroll
            for (int p = 0; p < 2; p++) {
                int kr = kn + bkk + p * 16;
                pb[p][0] = *(const float4*)(B + (size_t)kr * DD + n0 + bn8);
                pb[p][1] = *(const float4*)(B + (size_t)kr * DD + n0 + bn8 + 4);
            }
        }
        int arow = lane & 15, asel = (lane >> 4) * 8;
        #pragma unroll
        for (int kh = 0; kh < 2; kh++) {
            int k16 = kh * 16;
            uint32_t af[4][4], bf[4][2];
            #pragma unroll
            for (int i = 0; i < 4; i++)
                ldm_x4(af[i][0], af[i][1], af[i][2], af[i][3],
                       s2u(&As[cur][wm + i * 16 + arow][k16 + asel]));
            #pragma unroll
            for (int j = 0; j < 4; j++)
                ldm_x2t(bf[j][0], bf[j][1],
                        s2u(&Bs[cur][k16 + arow][wn + j * 8]));
            #pragma unroll
            for (int i = 0; i < 4; i++)
                #pragma unroll
                for (int j = 0; j < 4; j++) mma_f16(acc[i][j], af[i], bf[j]);
        }
        if (more) {
            #pragma unroll
            for (int p = 0; p < 2; p++) {
                uint4 v = A16 ? qa[p] : pack8(pa[p][0], pa[p][1]);
                *(uint4*)&As[nxt][am2 + p * 64][akv8] = v;
                *(uint4*)&Bs[nxt][bkk + p * 16][bn8] = pack8(pb[p][0], pb[p][1]);
            }
        }
        __syncthreads();
    }

    // epilogue: store h (fp16) + logit partials (warp's 32 cols = one head)
    int t2 = t4 * 2;
    float ps[8], pd[8];
    #pragma unroll
    for (int i = 0; i < 8; i++) { ps[i] = 0.f; pd[i] = 0.f; }
    #pragma unroll
    for (int i = 0; i < 4; i++) {
        int r = m0 + wm + i * 16 + g;
        #pragma unroll
        for (int j = 0; j < 4; j++) {
            int c = n0 + wn + j * 8 + t2;
            float a0 = a_src[c], a1 = a_src[c + 1];
            float d0 = a_dst[c], d1 = a_dst[c + 1];
            ps[i]     += acc[i][j][0] * a0 + acc[i][j][1] * a1;
            pd[i]     += acc[i][j][0] * d0 + acc[i][j][1] * d1;
            ps[i + 4] += acc[i][j][2] * a0 + acc[i][j][3] * a1;
            pd[i + 4] += acc[i][j][2] * d0 + acc[i][j][3] * d1;
            if (r < M)
                *(__half2*)(g_hh + (size_t)r * DD + c) =
                    __floats2half2_rn(acc[i][j][0], acc[i][j][1]);
            if (r + 8 < M)
                *(__half2*)(g_hh + (size_t)(r + 8) * DD + c) =
                    __floats2half2_rn(acc[i][j][2], acc[i][j][3]);
        }
    }
    #pragma unroll
    for (int i = 0; i < 8; i++) {
        #pragma unroll
        for (int o = 1; o < 4; o <<= 1) {
            ps[i] += __shfl_xor_sync(0xffffffffu, ps[i], o);
            pd[i] += __shfl_xor_sync(0xffffffffu, pd[i], o);
        }
    }
    if (t4 == 0) {
        #pragma unroll
        for (int i = 0; i < 4; i++) {
            int rl = wm + i * 16 + g;
            SPSa[rl][w] = ps[i];        SPDa[rl][w] = pd[i];
            SPSa[rl + 8][w] = ps[i + 4]; SPDa[rl + 8][w] = pd[i + 4];
        }
    }
    __syncthreads();
    if (tid < 128) {
        int r = tid;
        int b = (r >= 64) ? 1 : 0;
        float h0s = SPSa[r][b] + SPSa[r][b + 2];
        float h1s = SPSa[r][b + 4] + SPSa[r][b + 6];
        float h0d = SPDa[r][b] + SPDa[r][b + 2];
        float h1d = SPDa[r][b + 4] + SPDa[r][b + 6];
        int gr = m0 + r;
        if (gr < M) {
            g_als[gr * 4 + 2 * nb]     = h0s;
            g_als[gr * 4 + 2 * nb + 1] = h1s;
            g_ald[gr * 4 + 2 * nb]     = h0d;
            g_ald[gr * 4 + 2 * nb + 1] = h1d;
        }
    }
}

// ------- fused edge-softmax + aggregation, single pass (g_hh -> g_z16) -----
__global__ void k_agg(const float* __restrict__ bias) {
    int warp = (blockIdx.x * blockDim.x + threadIdx.x) >> 5;
    int lane = threadIdx.x & 31;
    if (warp >= NN) return;
    int n = warp;
    int start = g_off[n], end = g_off[n + 1];
    int myh = lane >> 3;
    float adh = g_ald[n * 4 + myh];
    const size_t cbase = (size_t)lane * 8;

    float den = 0.f;
    float4 acc0 = make_float4(0.f, 0.f, 0.f, 0.f);
    float4 acc1 = make_float4(0.f, 0.f, 0.f, 0.f);

    int i = start;
    for (; i + 2 <= end; i += 2) {
        int s0 = g_perm[i], s1 = g_perm[i + 1];
        float w0 = __expf(lrelu(g_als[s0 * 4 + myh] + adh));
        float w1 = __expf(lrelu(g_als[s1 * 4 + myh] + adh));
        uint4 r0 = *(const uint4*)(g_hh + (size_t)s0 * DD + cbase);
        uint4 r1 = *(const uint4*)(g_hh + (size_t)s1 * DD + cbase);
        const __half2* h0 = (const __half2*)&r0;
        const __half2* h1 = (const __half2*)&r1;
        float2 a = __half22float2(h0[0]), b = __half22float2(h0[1]);
        float2 c = __half22float2(h0[2]), d = __half22float2(h0[3]);
        float2 e = __half22float2(h1[0]), f = __half22float2(h1[1]);
        float2 p = __half22float2(h1[2]), q = __half22float2(h1[3]);
        den += w0 + w1;
        acc0.x += w0 * a.x + w1 * e.x; acc0.y += w0 * a.y + w1 * e.y;
        acc0.z += w0 * b.x + w1 * f.x; acc0.w += w0 * b.y + w1 * f.y;
        acc1.x += w0 * c.x + w1 * p.x; acc1.y += w0 * c.y + w1 * p.y;
        acc1.z += w0 * d.x + w1 * q.x; acc1.w += w0 * d.y + w1 * q.y;
    }
    if (i < end) {
        int s0 = g_perm[i];
        float w0 = __expf(lrelu(g_als[s0 * 4 + myh] + adh));
        uint4 r0 = *(const uint4*)(g_hh + (size_t)s0 * DD + cbase);
        const __half2* h0 = (const __half2*)&r0;
        float2 a = __half22float2(h0[0]), b = __half22float2(h0[1]);
        float2 c = __half22float2(h0[2]), d = __half22float2(h0[3]);
        den += w0;
        acc0.x += w0 * a.x; acc0.y += w0 * a.y;
        acc0.z += w0 * b.x; acc0.w += w0 * b.y;
        acc1.x += w0 * c.x; acc1.y += w0 * c.y;
        acc1.z += w0 * d.x; acc1.w += w0 * d.y;
    }
    float inv = 1.f / den;
    const float4* bp = (const float4*)(bias + cbase);
    float4 b0 = bp[0], b1 = bp[1];
    __half2 ho0 = __floats2half2_rn(eluf(acc0.x * inv + b0.x), eluf(acc0.y * inv + b0.y));
    __half2 ho1 = __floats2half2_rn(eluf(acc0.z * inv + b0.z), eluf(acc0.w * inv + b0.w));
    __half2 ho2 = __floats2half2_rn(eluf(acc1.x * inv + b1.x), eluf(acc1.y * inv + b1.y));
    __half2 ho3 = __floats2half2_rn(eluf(acc1.z * inv + b1.z), eluf(acc1.w * inv + b1.w));
    uint4 pk;
    pk.x = *(uint32_t*)&ho0; pk.y = *(uint32_t*)&ho1;
    pk.z = *(uint32_t*)&ho2; pk.w = *(uint32_t*)&ho3;
    *(uint4*)(g_z16 + (size_t)n * DD + cbase) = pk;
}

// -------- link scorer: fp16 gather-GEMM (A from g_z16) + fused MLP ---------
__global__ __launch_bounds__(256) void k_score_tc(
        const int* __restrict__ eli,
        const float* __restrict__ Ws1, const float* __restrict__ bs1,
        const float* __restrict__ Ws2, const float* __restrict__ bs2,
        float* __restrict__ out) {
    __shared__ __align__(16) __half As[128][40];
    __shared__ __align__(16) __half Bs[32][72];
    __shared__ int si0[128], si1[128];
    __shared__ float red[128][2];
    int tid = threadIdx.x, lane = tid & 31, w = tid >> 5;
    int m0 = blockIdx.x * 128;
    int wm = (w & 3) * 32, wn = (w >> 2) * 32;
    int g = lane >> 2, t4 = lane & 3;

    if (tid < 128) {
        int gm = m0 + tid;
        si0[tid] = (gm < ELn) ? eli[gm] : 0;
        si1[tid] = (gm < ELn) ? eli[ELn + gm] : 0;
    }
    __syncthreads();

    float acc[2][4][4];
    #pragma unroll
    for (int i = 0; i < 2; i++)
        #pragma unroll
        for (int j = 0; j < 4; j++)
            #pragma unroll
            for (int q = 0; q < 4; q++) acc[i][j][q] = 0.f;

    int am2 = tid >> 2, akv8 = (tid & 3) * 8;
    int bkk = tid >> 3, bn8 = (tid & 7) * 8;

    uint4 qa[2]; float4 pb[2];
    #pragma unroll
    for (int p = 0; p < 2; p++) {
        int m = am2 + p * 64;
        qa[p] = *(const uint4*)(g_z16 + (size_t)si0[m] * DD + akv8);
    }
    pb[0] = *(const float4*)(Ws1 + (size_t)bkk * 64 + bn8);
    pb[1] = *(const float4*)(Ws1 + (size_t)bkk * 64 + bn8 + 4);

    for (int k0 = 0; k0 < 512; k0 += 32) {
        #pragma unroll
        for (int p = 0; p < 2; p++)
            *(uint4*)&As[am2 + p * 64][akv8] = qa[p];
        *(uint4*)&Bs[bkk][bn8] = pack8(pb[0], pb[1]);
        __syncthreads();
        int kn = k0 + 32;
        if (kn < 512) {
            int kk = kn + akv8;
            #pragma unroll
            for (int p = 0; p < 2; p++) {
                int m = am2 + p * 64;
                int row = (kk < 256) ? si0[m] : si1[m];
                qa[p] = *(const uint4*)(g_z16 + (size_t)row * DD + (kk & 255));
            }
            pb[0] = *(const float4*)(Ws1 + (size_t)(kn + bkk) * 64 + bn8);
            pb[1] = *(const float4*)(Ws1 + (size_t)(kn + bkk) * 64 + bn8 + 4);
        }
        int arow = lane & 15, asel = (lane >> 4) * 8;
        #pragma unroll
        for (int kh = 0; kh < 2; kh++) {
            int k16 = kh * 16;
            uint32_t af[2][4], bf[4][2];
            #pragma unroll
            for (int i = 0; i < 2; i++)
                ldm_x4(af[i][0], af[i][1], af[i][2], af[i][3],
                       s2u(&As[wm + i * 16 + arow][k16 + asel]));
            #pragma unroll
            for (int j = 0; j < 4; j++)
                ldm_x2t(bf[j][0], bf[j][1],
                        s2u(&Bs[k16 + arow][wn + j * 8]));
            #pragma unroll
            for (int i = 0; i < 2; i++)
                #pragma unroll
                for (int j = 0; j < 4; j++) mma_f16(acc[i][j], af[i], bf[j]);
        }
        __syncthreads();
    }
    int t2 = t4 * 2;
    float p00 = 0.f, p01 = 0.f, p10 = 0.f, p11 = 0.f;
    #pragma unroll
    for (int j = 0; j < 4; j++) {
        int c0 = wn + j * 8 + t2;
        float bv0 = bs1[c0], bv1 = bs1[c0 + 1];
        float w0 = Ws2[c0], w1 = Ws2[c0 + 1];
        p00 += fmaxf(acc[0][j][0] + bv0, 0.f) * w0 + fmaxf(acc[0][j][1] + bv1, 0.f) * w1;
        p01 += fmaxf(acc[0][j][2] + bv0, 0.f) * w0 + fmaxf(acc[0][j][3] + bv1, 0.f) * w1;
        p10 += fmaxf(acc[1][j][0] + bv0, 0.f) * w0 + fmaxf(acc[1][j][1] + bv1, 0.f) * w1;
        p11 += fmaxf(acc[1][j][2] + bv0, 0.f) * w0 + fmaxf(acc[1][j][3] + bv1, 0.f) * w1;
    }
    #pragma unroll
    for (int o = 1; o < 4; o <<= 1) {
        p00 += __shfl_xor_sync(0xffffffffu, p00, o);
        p01 += __shfl_xor_sync(0xffffffffu, p01, o);
        p10 += __shfl_xor_sync(0xffffffffu, p10, o);
        p11 += __shfl_xor_sync(0xffffffffu, p11, o);
    }
    int wnidx = w >> 2;
    if (t4 == 0) {
        red[wm + g][wnidx]      = p00;
        red[wm + 8 + g][wnidx]  = p01;
        red[wm + 16 + g][wnidx] = p10;
        red[wm + 24 + g][wnidx] = p11;
    }
    __syncthreads();
    if (tid < 128) {
        int gm = m0 + tid;
        if (gm < ELn) out[gm] = red[tid][0] + red[tid][1] + bs2[0];
    }
}

// ---------------- launch ---------------------------------------------------
extern "C" void kernel_launch(void* const* d_in, const int* in_sizes, int n_in,
                              void* d_out, int out_size) {
    const float* x   = (const float*)d_in[0];
    const int*   ei  = (const int*)d_in[1];
    const int*   eli = (const int*)d_in[2];
    const float* W1  = (const float*)d_in[3];
    const float* as1 = (const float*)d_in[4];
    const float* ad1 = (const float*)d_in[5];
    const float* b1  = (const float*)d_in[6];
    const float* W2  = (const float*)d_in[7];
    const float* as2 = (const float*)d_in[8];
    const float* ad2 = (const float*)d_in[9];
    const float* b2  = (const float*)d_in[10];
    const float* Ws1 = (const float*)d_in[11];
    const float* bs1 = (const float*)d_in[12];
    const float* Ws2 = (const float*)d_in[13];
    const float* bs2 = (const float*)d_in[14];
    float* out = (float*)d_out;

    // side stream for the CSR build, overlapped with GEMM-1
    // (created per call and intentionally leaked; no device memory involved)
    cudaStream_t s1;
    cudaStreamCreateWithFlags(&s1, cudaStreamNonBlocking);
    cudaEvent_t evFork, evJoin;
    cudaEventCreateWithFlags(&evFork, cudaEventDisableTiming);
    cudaEventCreateWithFlags(&evJoin, cudaEventDisableTiming);

    cudaEventRecord(evFork, 0);
    cudaStreamWaitEvent(s1, evFork, 0);
    k_zero<<<(NN + 256) / 256, 256, 0, s1>>>();
    k_hist<<<(E4CNT + 255) / 256, 256, 0, s1>>>(ei);
    k_scan<<<1, 1024, 0, s1>>>();
    k_scatter<<<(E4CNT + NN + 255) / 256, 256, 0, s1>>>(ei);
    cudaEventRecord(evJoin, s1);

    dim3 gg((NN + 127) / 128, 2);

    // layer 1 GEMM on main stream, concurrent with CSR build
    k_gemm_tc<0><<<gg, 256>>>(x, W1, as1, ad1, NN, 128);
    cudaStreamWaitEvent(0, evJoin, 0);
    k_agg<<<(NN + 7) / 8, 256>>>(b1);

    // layer 2:  g_z16 @ W2 -> g_hh (+ final logits) ; agg -> g_z16
    k_gemm_tc<1><<<gg, 256>>>(nullptr, W2, as2, ad2, NN, 256);
    k_agg<<<(NN + 7) / 8, 256>>>(b2);

    // scorer
    k_score_tc<<<(ELn + 127) / 128, 256>>>(eli, Ws1, bs1, Ws2, bs2, out);
}